// round 3
// baseline (speedup 1.0000x reference)
#include <cuda_runtime.h>
#include <cuda_bf16.h>

#define NN 100000
#define NE 3200000

// ---------------- scratch (device globals: allocation-free) ----------------
__device__ int2   g_edges[NE];   // packed (row=dst, col=src) as int32
__device__ int    g_deg[NN];
__device__ float  g_dinv[NN];
__device__ float4 g_t4[NN];      // current layer's scaled node features (gather source)
__device__ float4 g_aggA[NN];    // layer-1 accumulator
__device__ float4 g_aggB[NN];    // layer-2 accumulator
__device__ float2 g_t2[NN];      // layer-3 scaled features
__device__ float2 g_agg2[NN];    // layer-3 accumulator
__device__ int    g_idx32;       // 1 if edge_index is int32, 0 if int64

// ---------------- dtype detection ----------------
__global__ void k_detect(const long long* __restrict__ ei) {
    if (threadIdx.x == 0 && blockIdx.x == 0) {
        int bad = 0;
        #pragma unroll 1
        for (int i = 0; i < 64; i++) {
            long long v = ei[i];
            if (v < 0 || v >= NN) { bad = 1; break; }
        }
        g_idx32 = bad;
    }
}

// ---------------- preprocessing ----------------
__global__ void k_init_deg() {
    int v = blockIdx.x * blockDim.x + threadIdx.x;
    if (v < NN) g_deg[v] = 1;            // self-loop
}

__global__ void k_pre(const void* __restrict__ eiv) {
    int e = blockIdx.x * blockDim.x + threadIdx.x;
    if (e >= NE) return;
    int r, c;
    if (g_idx32) {
        const int* ei = (const int*)eiv;
        r = ei[e];                 // edge_index[0][e] : destination (row)
        c = ei[NE + e];            // edge_index[1][e] : source (col)
    } else {
        const long long* ei = (const long long*)eiv;
        r = (int)ei[e];
        c = (int)ei[NE + e];
    }
    g_edges[e] = make_int2(r, c);
    atomicAdd(&g_deg[c], 1);       // degree counts SOURCE occurrences (matches ref)
}

__global__ void k_dinv() {
    int v = blockIdx.x * blockDim.x + threadIdx.x;
    if (v < NN) g_dinv[v] = rsqrtf((float)g_deg[v]);
}

// ---------------- layer 1 transform: t = (x @ W1) * dinv ; agg = t (self-loop) ----
// warp per node; 128 features; thread t handles features [4t, 4t+3]
__global__ void __launch_bounds__(256) k_l1(const float* __restrict__ x,
                                            const float* __restrict__ W1) {
    __shared__ float sW[512];            // W1 [128,4] row-major
    for (int i = threadIdx.x; i < 512; i += 256) sW[i] = W1[i];
    __syncthreads();
    int gw   = (blockIdx.x * 256 + threadIdx.x) >> 5;   // node
    int lane = threadIdx.x & 31;
    if (gw >= NN) return;
    float4 xr = __ldg((const float4*)x + (size_t)gw * 32 + lane);
    float xs[4] = {xr.x, xr.y, xr.z, xr.w};
    float acc[4] = {0.f, 0.f, 0.f, 0.f};
    #pragma unroll
    for (int i = 0; i < 4; i++) {
        int k = lane * 4 + i;
        #pragma unroll
        for (int j = 0; j < 4; j++) acc[j] += xs[i] * sW[k * 4 + j];
    }
    #pragma unroll
    for (int off = 16; off > 0; off >>= 1) {
        #pragma unroll
        for (int j = 0; j < 4; j++)
            acc[j] += __shfl_xor_sync(0xffffffffu, acc[j], off);
    }
    if (lane == 0) {
        float d  = g_dinv[gw];
        float4 t = make_float4(acc[0] * d, acc[1] * d, acc[2] * d, acc[3] * d);
        g_t4[gw]   = t;
        g_aggA[gw] = t;                 // self-loop contribution
    }
}

// ---------------- edge scatter: agg[row] += t[col] ----------------
template <int PHASE>   // 0: agg=aggA, 1: agg=aggB
__global__ void __launch_bounds__(256) k_scatter4() {
    int e = blockIdx.x * blockDim.x + threadIdx.x;
    if (e >= NE) return;
    int2 rc = g_edges[e];
    float4 v = __ldg(g_t4 + rc.y);
    float4* agg = (PHASE == 0) ? g_aggA : g_aggB;
    asm volatile("red.global.add.v4.f32 [%0], {%1, %2, %3, %4};"
                 :: "l"(agg + rc.x), "f"(v.x), "f"(v.y), "f"(v.z), "f"(v.w)
                 : "memory");
}

__global__ void __launch_bounds__(256) k_scatter2() {
    int e = blockIdx.x * blockDim.x + threadIdx.x;
    if (e >= NE) return;
    int2 rc = g_edges[e];
    float2 v = __ldg(g_t2 + rc.y);
    asm volatile("red.global.add.v2.f32 [%0], {%1, %2};"
                 :: "l"(g_agg2 + rc.x), "f"(v.x), "f"(v.y)
                 : "memory");
}

// ---------------- layer 2 transform: h1 = tanh(dinv*aggA + b1); t = (h1@W2)*dinv ----
__global__ void __launch_bounds__(256) k_l2(const float* __restrict__ W2,
                                            const float* __restrict__ b1) {
    int v = blockIdx.x * blockDim.x + threadIdx.x;
    if (v >= NN) return;
    float d  = g_dinv[v];
    float4 a = g_aggA[v];
    float h0 = tanhf(fmaf(a.x, d, __ldg(b1 + 0)));
    float h1 = tanhf(fmaf(a.y, d, __ldg(b1 + 1)));
    float h2 = tanhf(fmaf(a.z, d, __ldg(b1 + 2)));
    float h3 = tanhf(fmaf(a.w, d, __ldg(b1 + 3)));
    float t[4];
    #pragma unroll
    for (int j = 0; j < 4; j++)
        t[j] = (h0 * __ldg(W2 + j)     + h1 * __ldg(W2 + 4 + j)
              + h2 * __ldg(W2 + 8 + j) + h3 * __ldg(W2 + 12 + j)) * d;
    float4 tv = make_float4(t[0], t[1], t[2], t[3]);
    g_t4[v]   = tv;
    g_aggB[v] = tv;
}

// ---------------- layer 3 transform: h2 = tanh(dinv*aggB + b2); t = (h2@W3)*dinv ----
__global__ void __launch_bounds__(256) k_l3(const float* __restrict__ W3,
                                            const float* __restrict__ b2) {
    int v = blockIdx.x * blockDim.x + threadIdx.x;
    if (v >= NN) return;
    float d  = g_dinv[v];
    float4 a = g_aggB[v];
    float h0 = tanhf(fmaf(a.x, d, __ldg(b2 + 0)));
    float h1 = tanhf(fmaf(a.y, d, __ldg(b2 + 1)));
    float h2 = tanhf(fmaf(a.z, d, __ldg(b2 + 2)));
    float h3 = tanhf(fmaf(a.w, d, __ldg(b2 + 3)));
    float t0 = (h0 * __ldg(W3 + 0) + h1 * __ldg(W3 + 2)
              + h2 * __ldg(W3 + 4) + h3 * __ldg(W3 + 6)) * d;
    float t1 = (h0 * __ldg(W3 + 1) + h1 * __ldg(W3 + 3)
              + h2 * __ldg(W3 + 5) + h3 * __ldg(W3 + 7)) * d;
    float2 tv = make_float2(t0, t1);
    g_t2[v]   = tv;
    g_agg2[v] = tv;
}

// ---------------- epilogue: h3 = tanh(dinv*agg2 + b3); out = h3@Wc + bc ----------
__global__ void __launch_bounds__(256) k_final(const float* __restrict__ b3,
                                               const float* __restrict__ Wc,
                                               const float* __restrict__ bc,
                                               float* __restrict__ out,
                                               int write_h) {
    int v = blockIdx.x * blockDim.x + threadIdx.x;
    if (v >= NN) return;
    float d  = g_dinv[v];
    float2 a = g_agg2[v];
    float h0 = tanhf(fmaf(a.x, d, __ldg(b3 + 0)));
    float h1 = tanhf(fmaf(a.y, d, __ldg(b3 + 1)));
    float4 o;
    o.x = h0 * __ldg(Wc + 0) + h1 * __ldg(Wc + 4) + __ldg(bc + 0);
    o.y = h0 * __ldg(Wc + 1) + h1 * __ldg(Wc + 5) + __ldg(bc + 1);
    o.z = h0 * __ldg(Wc + 2) + h1 * __ldg(Wc + 6) + __ldg(bc + 2);
    o.w = h0 * __ldg(Wc + 3) + h1 * __ldg(Wc + 7) + __ldg(bc + 3);
    ((float4*)out)[v] = o;                                 // out [N,4]
    if (write_h)
        ((float2*)(out + 4 * NN))[v] = make_float2(h0, h1); // h [N,2]
}

// ---------------- host ----------------
extern "C" void kernel_launch(void* const* d_in, const int* in_sizes, int n_in,
                              void* d_out, int out_size) {
    const float* x  = (const float*)d_in[0];
    const void*  ei = d_in[1];
    const float* W1 = (const float*)d_in[2];
    const float* b1 = (const float*)d_in[3];
    const float* W2 = (const float*)d_in[4];
    const float* b2 = (const float*)d_in[5];
    const float* W3 = (const float*)d_in[6];
    const float* b3 = (const float*)d_in[7];
    const float* Wc = (const float*)d_in[8];
    const float* bc = (const float*)d_in[9];
    float* out = (float*)d_out;

    const int nbN = (NN + 255) / 256;
    const int nbE = (NE + 255) / 256;
    const int nbW = (NN + 7) / 8;      // warp-per-node, 8 warps/block
    const int write_h = (out_size >= 6 * NN) ? 1 : 0;

    k_detect  <<<1, 32>>>((const long long*)ei);
    k_init_deg<<<nbN, 256>>>();
    k_pre     <<<nbE, 256>>>(ei);
    k_dinv    <<<nbN, 256>>>();

    k_l1        <<<nbW, 256>>>(x, W1);
    k_scatter4<0><<<nbE, 256>>>();

    k_l2        <<<nbN, 256>>>(W2, b1);
    k_scatter4<1><<<nbE, 256>>>();

    k_l3        <<<nbN, 256>>>(W3, b2);
    k_scatter2  <<<nbE, 256>>>();

    k_final     <<<nbN, 256>>>(b3, Wc, bc, out, write_h);
}